// round 13
// baseline (speedup 1.0000x reference)
#include <cuda_runtime.h>
#include <cuda_fp16.h>
#include <mma.h>
using namespace nvcuda;

// Problem constants (fixed by the dataset)
#define F_DIM   128
#define MAXN    10240
#define MAXE    655360
#define ATT_SCALE 0.17677669529663687f   // 1/sqrt(32)
#define LN_EPS  1e-5f
#define MBLK 64
#define NBLK 64
#define A_LD 132
#define B_LD 68
#define SMEM_FLOATS (MBLK * A_LD + 128 * B_LD)

// ---------------- scratch (device globals; no allocation allowed) -------------
__device__ float  g_Q[MAXN * F_DIM];
__device__ __half g_KV[MAXN * 256];      // per node: 128 K halfs then 128 V halfs
__device__ float  g_R[MAXN * F_DIM];
__device__ int    g_counts[MAXN];
__device__ int    g_offs[MAXN + 1];
__device__ int    g_rank[MAXE];          // per-edge rank within its dst segment
__device__ int    g_srcsorted[MAXE];

// ---------------- K1: tensor-core QKVR projections + dst histogram+rank --------
// grid = (ceil(N/64), 8). blockIdx.y picks a 64-col slice of the 512 output
// columns (4 matrices x 128). BOTH A (X tile) and B (W tile) staged in smem via
// coalesced float4 loads with inline tf32 rounding; all wmma loads hit smem.
__global__ __launch_bounds__(128) void k_qkv_tc(
    const float* __restrict__ X,
    const float* __restrict__ WQ, const float* __restrict__ WK,
    const float* __restrict__ WV, const float* __restrict__ WR,
    const float* __restrict__ br,
    const int* __restrict__ dst, int N, int E, int epb)
{
    extern __shared__ float sh[];
    float* As = sh;                      // [64][132]
    float* Bs = sh + MBLK * A_LD;        // [128][68]

    const int tid  = threadIdx.x;
    const int w    = tid >> 5;
    const int lane = tid & 31;

    const int ncol0 = blockIdx.y * NBLK;
    const int mat   = ncol0 >> 7;        // 0=Q 1=K 2=V 3=R
    const int c0    = ncol0 & 127;
    const float* __restrict__ W =
        (mat == 0) ? WQ : (mat == 1) ? WK : (mat == 2) ? WV : WR;

    // stage A tile [64 x 128] (coalesced float4, tf32-rounded, zero-padded)
    const int m0base = blockIdx.x * MBLK;
    #pragma unroll
    for (int i = tid; i < MBLK * 32; i += 128) {
        const int row = i >> 5, c4 = (i & 31) << 2;
        const int node = m0base + row;
        float4 v = make_float4(0.f, 0.f, 0.f, 0.f);
        if (node < N) v = *reinterpret_cast<const float4*>(X + node * F_DIM + c4);
        float* d = As + row * A_LD + c4;
        d[0] = wmma::__float_to_tf32(v.x);
        d[1] = wmma::__float_to_tf32(v.y);
        d[2] = wmma::__float_to_tf32(v.z);
        d[3] = wmma::__float_to_tf32(v.w);
    }

    // stage W tile [128 x 64] (tf32-rounded)
    for (int i = tid; i < 128 * 64; i += 128) {
        const int f = i >> 6, c = i & 63;
        Bs[f * B_LD + c] = wmma::__float_to_tf32(__ldg(&W[f * F_DIM + c0 + c]));
    }
    __syncthreads();

    wmma::fragment<wmma::accumulator, 16, 16, 8, float> acc[4];
    #pragma unroll
    for (int j = 0; j < 4; ++j) wmma::fill_fragment(acc[j], 0.f);

    #pragma unroll
    for (int k = 0; k < F_DIM; k += 8) {
        wmma::fragment<wmma::matrix_a, 16, 16, 8, wmma::precision::tf32,
                       wmma::row_major> a;
        wmma::load_matrix_sync(a, As + (w * 16) * A_LD + k, A_LD);
        #pragma unroll
        for (int j = 0; j < 4; ++j) {
            wmma::fragment<wmma::matrix_b, 16, 16, 8, wmma::precision::tf32,
                           wmma::row_major> b;
            wmma::load_matrix_sync(b, Bs + k * B_LD + j * 16, B_LD);
            wmma::mma_sync(acc[j], a, b, acc[j]);
        }
    }

    // epilogue: stage through smem (alias A region after barrier), typed stores
    __syncthreads();
    float* Cw = As + w * (16 * B_LD);
    #pragma unroll
    for (int j = 0; j < 4; ++j)
        wmma::store_matrix_sync(Cw + j * 16, acc[j], B_LD, wmma::mem_row_major);
    __syncwarp();

    const int m0 = m0base + w * 16;
    for (int r = 0; r < 16; ++r) {
        const int node = m0 + r;
        if (node >= N) break;
        #pragma unroll
        for (int c = lane; c < 64; c += 32) {
            const float v = Cw[r * B_LD + c];
            const int col = c0 + c;
            if      (mat == 0) g_Q[node * F_DIM + col] = v;
            else if (mat == 1) g_KV[node * 256 + col]       = __float2half_rn(v);
            else if (mat == 2) g_KV[node * 256 + 128 + col] = __float2half_rn(v);
            else               g_R[node * F_DIM + col] = v + __ldg(&br[col]);
        }
    }

    // fused dst histogram + rank capture: this block's edge slice
    const int bid = blockIdx.y * gridDim.x + blockIdx.x;
    const int e0 = bid * epb;
    const int e1 = min(e0 + epb, E);
    for (int e = e0 + tid; e < e1; e += 128)
        g_rank[e] = atomicAdd(&g_counts[__ldg(&dst[e])], 1);
}

// ---------------- K2: exclusive scan (warp-shuffle, 2 barriers) ----------------
__global__ __launch_bounds__(1024) void k_scan(int N, int E) {
    __shared__ int wsum[32];
    const int t = threadIdx.x;
    const int lane = t & 31, w = t >> 5;
    const int base = t * 10;             // 1024*10 = 10240 >= MAXN

    int loc[10];
    int s = 0;
    #pragma unroll
    for (int i = 0; i < 10; ++i) {
        const int idx = base + i;
        loc[i] = (idx < N) ? g_counts[idx] : 0;
        s += loc[i];
    }
    int inc = s;
    #pragma unroll
    for (int o = 1; o < 32; o <<= 1) {
        int v = __shfl_up_sync(0xffffffffu, inc, o);
        if (lane >= o) inc += v;
    }
    if (lane == 31) wsum[w] = inc;
    __syncthreads();
    if (w == 0) {
        int v = wsum[lane];
        #pragma unroll
        for (int o = 1; o < 32; o <<= 1) {
            int u = __shfl_up_sync(0xffffffffu, v, o);
            if (lane >= o) v += u;
        }
        wsum[lane] = v;
    }
    __syncthreads();
    int run = ((w == 0) ? 0 : wsum[w - 1]) + (inc - s);  // exclusive prefix
    #pragma unroll
    for (int i = 0; i < 10; ++i) {
        const int idx = base + i;
        if (idx < N) g_offs[idx] = run, run += loc[i];
    }
    if (t == 0) g_offs[N] = E;
}

// ---------------- K3: scatter edges into CSR order (NO atomics) ----------------
__global__ __launch_bounds__(256) void k_scatter(
    const int* __restrict__ src, const int* __restrict__ dst, int E)
{
    const int base = (blockIdx.x * blockDim.x + threadIdx.x) * 4;
    if (base + 3 < E) {
        const int4 d = *reinterpret_cast<const int4*>(dst + base);
        const int4 s = *reinterpret_cast<const int4*>(src + base);
        const int4 r = *reinterpret_cast<const int4*>(g_rank + base);
        g_srcsorted[g_offs[d.x] + r.x] = s.x;
        g_srcsorted[g_offs[d.y] + r.y] = s.y;
        g_srcsorted[g_offs[d.z] + r.z] = s.z;
        g_srcsorted[g_offs[d.w] + r.w] = s.w;
    } else {
        for (int e = base; e < E; ++e)
            g_srcsorted[g_offs[dst[e]] + g_rank[e]] = src[e];
    }
}

// ---------------- K4: fused attention + residual + LayerNorm -------------------
__global__ __launch_bounds__(256) void k_attn(
    const float* __restrict__ gamma, const float* __restrict__ beta,
    float* __restrict__ out, int N)
{
    const int warp = (blockIdx.x * blockDim.x + threadIdx.x) >> 5;
    if (warp >= N) return;
    const int lane = threadIdx.x & 31;

    float4 q = ((const float4*)g_Q)[warp * 32 + lane];
    q.x *= ATT_SCALE; q.y *= ATT_SCALE; q.z *= ATT_SCALE; q.w *= ATT_SCALE;

    const uint2* __restrict__ KV = (const uint2*)g_KV;   // 64 uint2 per node row

    float4 acc = make_float4(0.f, 0.f, 0.f, 0.f);
    float ssum = 0.f;

    const int beg = g_offs[warp];
    const int end = g_offs[warp + 1];

    for (int base = beg; base < end; base += 32) {
        const int idx = base + lane;
        const int mysrc = (idx < end) ? g_srcsorted[idx] : 0;
        const int cnt = min(32, end - base);
        for (int j = 0; j < cnt; ++j) {
            const int src = __shfl_sync(0xffffffffu, mysrc, j);
            const uint2 ku = KV[src * 64 + lane];
            const uint2 vu = KV[src * 64 + 32 + lane];
            const float2 k0 = __half22float2(*(const __half2*)&ku.x);
            const float2 k1 = __half22float2(*(const __half2*)&ku.y);
            float p = q.x * k0.x + q.y * k0.y + q.z * k1.x + q.w * k1.y;
            p += __shfl_xor_sync(0xffffffffu, p, 1);
            p += __shfl_xor_sync(0xffffffffu, p, 2);
            p += __shfl_xor_sync(0xffffffffu, p, 4);
            const float wgt = __expf(p);
            const float2 v0 = __half22float2(*(const __half2*)&vu.x);
            const float2 v1 = __half22float2(*(const __half2*)&vu.y);
            ssum += wgt;
            acc.x = fmaf(wgt, v0.x, acc.x);
            acc.y = fmaf(wgt, v0.y, acc.y);
            acc.z = fmaf(wgt, v1.x, acc.z);
            acc.w = fmaf(wgt, v1.y, acc.w);
        }
    }

    const float inv = 1.f / (ssum + 1e-12f);
    const float4 r = ((const float4*)g_R)[warp * 32 + lane];
    float4 h;
    h.x = fmaf(acc.x, inv, r.x);
    h.y = fmaf(acc.y, inv, r.y);
    h.z = fmaf(acc.z, inv, r.z);
    h.w = fmaf(acc.w, inv, r.w);

    float s1 = h.x + h.y + h.z + h.w;
    float s2 = h.x * h.x + h.y * h.y + h.z * h.z + h.w * h.w;
    #pragma unroll
    for (int o = 16; o; o >>= 1) {
        s1 += __shfl_xor_sync(0xffffffffu, s1, o);
        s2 += __shfl_xor_sync(0xffffffffu, s2, o);
    }
    const float mu  = s1 * (1.f / 128.f);
    const float var = s2 * (1.f / 128.f) - mu * mu;
    const float rs  = rsqrtf(var + LN_EPS);

    const float4 g = ((const float4*)gamma)[lane];
    const float4 b = ((const float4*)beta)[lane];
    float4 o4;
    o4.x = fmaf(g.x * (h.x - mu), rs, b.x);
    o4.y = fmaf(g.y * (h.y - mu), rs, b.y);
    o4.z = fmaf(g.z * (h.z - mu), rs, b.z);
    o4.w = fmaf(g.w * (h.w - mu), rs, b.w);
    ((float4*)out)[warp * 32 + lane] = o4;
}

// ---------------- launch -------------------------------------------------------
extern "C" void kernel_launch(void* const* d_in, const int* in_sizes, int n_in,
                              void* d_out, int out_size)
{
    const float* nodes = (const float*)d_in[0];
    const float* WQ    = (const float*)d_in[1];
    const float* WK    = (const float*)d_in[2];
    const float* WV    = (const float*)d_in[3];
    const float* WR    = (const float*)d_in[4];
    const float* br    = (const float*)d_in[5];
    const float* gamma = (const float*)d_in[6];
    const float* beta  = (const float*)d_in[7];
    const int*   ei    = (const int*)d_in[8];

    const int N = in_sizes[0] / F_DIM;
    const int E = in_sizes[8] / 2;
    const int* src = ei;
    const int* dst = ei + E;

    const int mblocks = (N + MBLK - 1) / MBLK;
    const int nblk    = mblocks * 8;
    const int epb     = (E + nblk - 1) / nblk;
    const int smem_b  = SMEM_FLOATS * sizeof(float);   // ~68.6 KB

    cudaFuncSetAttribute(k_qkv_tc,
        cudaFuncAttributeMaxDynamicSharedMemorySize, smem_b);

    void* cnt_ptr = nullptr;
    cudaGetSymbolAddress(&cnt_ptr, g_counts);
    cudaMemsetAsync(cnt_ptr, 0, N * sizeof(int));

    dim3 grid_tc(mblocks, 8);
    k_qkv_tc<<<grid_tc, 128, smem_b>>>(nodes, WQ, WK, WV, WR, br, dst, N, E, epb);
    k_scan<<<1, 1024>>>(N, E);
    k_scatter<<<((E + 3) / 4 + 255) / 256, 256>>>(src, dst, E);
    k_attn<<<(N + 7) / 8, 256>>>(gamma, beta, (float*)d_out, N);
}

// round 14
// speedup vs baseline: 1.2096x; 1.2096x over previous
#include <cuda_runtime.h>
#include <cuda_fp16.h>
#include <mma.h>
using namespace nvcuda;

// Problem constants (fixed by the dataset)
#define F_DIM   128
#define MAXN    10240
#define MAXE    655360
#define ATT_SCALE 0.17677669529663687f   // 1/sqrt(32)
#define LN_EPS  1e-5f
#define MBLK 64
#define NBLK 64

// ---------------- scratch (device globals; no allocation allowed) -------------
__device__ float  g_Xpad[MAXN * F_DIM];  // tf32-rounded, zero-padded X
__device__ __half g_Qh[MAXN * F_DIM];    // fp16 Q, pre-scaled by ATT_SCALE
__device__ __half g_KV[MAXN * 256];      // per node: 128 K halfs then 128 V halfs
__device__ float  g_R[MAXN * F_DIM];
__device__ int    g_counts[MAXN];
__device__ int    g_offs[MAXN + 1];
__device__ int    g_rank[MAXE];          // per-edge rank within its dst segment
__device__ int    g_srcsorted[MAXE];

// ---------------- K0: copy X -> tf32-rounded zero-padded buffer ----------------
__global__ void k_copyX(const float* __restrict__ X, int N, int padN) {
    const int i = blockIdx.x * 256 + threadIdx.x;
    const int node = i >> 7;
    if (node < padN)
        g_Xpad[i] = (node < N) ? wmma::__float_to_tf32(X[i]) : 0.f;
}

// ---------------- K1: tensor-core QKVR projections + dst histogram+rank --------
// (R11 configuration — measured good.) grid = (ceil(N/64), 8).
__global__ __launch_bounds__(128) void k_qkv_tc(
    const float* __restrict__ WQ, const float* __restrict__ WK,
    const float* __restrict__ WV, const float* __restrict__ WR,
    const float* __restrict__ br,
    const int* __restrict__ dst, int N, int E, int epb)
{
    __shared__ float Bs[128][68];        // [k][n], tf32-rounded; 34.8 KB

    const int tid  = threadIdx.x;
    const int w    = tid >> 5;
    const int lane = tid & 31;

    const int ncol0 = blockIdx.y * NBLK;
    const int mat   = ncol0 >> 7;        // 0=Q 1=K 2=V 3=R
    const int c0    = ncol0 & 127;
    const float* __restrict__ W =
        (mat == 0) ? WQ : (mat == 1) ? WK : (mat == 2) ? WV : WR;

    for (int i = tid; i < 128 * 64; i += 128) {
        const int f = i >> 6, c = i & 63;
        Bs[f][c] = wmma::__float_to_tf32(__ldg(&W[f * F_DIM + c0 + c]));
    }
    __syncthreads();

    const int m0 = blockIdx.x * MBLK + w * 16;
    const float* Arow = g_Xpad + m0 * F_DIM;

    wmma::fragment<wmma::accumulator, 16, 16, 8, float> acc[4];
    #pragma unroll
    for (int j = 0; j < 4; ++j) wmma::fill_fragment(acc[j], 0.f);

    #pragma unroll
    for (int k = 0; k < F_DIM; k += 8) {
        wmma::fragment<wmma::matrix_a, 16, 16, 8, wmma::precision::tf32,
                       wmma::row_major> a;
        wmma::load_matrix_sync(a, Arow + k, F_DIM);
        #pragma unroll
        for (int j = 0; j < 4; ++j) {
            wmma::fragment<wmma::matrix_b, 16, 16, 8, wmma::precision::tf32,
                           wmma::row_major> b;
            wmma::load_matrix_sync(b, &Bs[k][j * 16], 68);
            wmma::mma_sync(acc[j], a, b, acc[j]);
        }
    }

    __syncthreads();
    float* Cw = reinterpret_cast<float*>(Bs) + w * (16 * 68);
    #pragma unroll
    for (int j = 0; j < 4; ++j)
        wmma::store_matrix_sync(Cw + j * 16, acc[j], 68, wmma::mem_row_major);
    __syncwarp();

    for (int r = 0; r < 16; ++r) {
        const int node = m0 + r;
        if (node >= N) break;
        #pragma unroll
        for (int c = lane; c < 64; c += 32) {
            const float v = Cw[r * 68 + c];
            const int col = c0 + c;
            if      (mat == 0) g_Qh[node * F_DIM + col] =
                                   __float2half_rn(v * ATT_SCALE);
            else if (mat == 1) g_KV[node * 256 + col]       = __float2half_rn(v);
            else if (mat == 2) g_KV[node * 256 + 128 + col] = __float2half_rn(v);
            else               g_R[node * F_DIM + col] = v + __ldg(&br[col]);
        }
    }

    // fused dst histogram + rank capture
    const int bid = blockIdx.y * gridDim.x + blockIdx.x;
    const int e0 = bid * epb;
    const int e1 = min(e0 + epb, E);
    for (int e = e0 + tid; e < e1; e += 128)
        g_rank[e] = atomicAdd(&g_counts[__ldg(&dst[e])], 1);
}

// ---------------- K2: exclusive scan (warp-shuffle, 2 barriers) ----------------
__global__ __launch_bounds__(1024) void k_scan(int N, int E) {
    __shared__ int wsum[32];
    const int t = threadIdx.x;
    const int lane = t & 31, w = t >> 5;
    const int base = t * 10;

    int loc[10];
    int s = 0;
    #pragma unroll
    for (int i = 0; i < 10; ++i) {
        const int idx = base + i;
        loc[i] = (idx < N) ? g_counts[idx] : 0;
        s += loc[i];
    }
    int inc = s;
    #pragma unroll
    for (int o = 1; o < 32; o <<= 1) {
        int v = __shfl_up_sync(0xffffffffu, inc, o);
        if (lane >= o) inc += v;
    }
    if (lane == 31) wsum[w] = inc;
    __syncthreads();
    if (w == 0) {
        int v = wsum[lane];
        #pragma unroll
        for (int o = 1; o < 32; o <<= 1) {
            int u = __shfl_up_sync(0xffffffffu, v, o);
            if (lane >= o) v += u;
        }
        wsum[lane] = v;
    }
    __syncthreads();
    int run = ((w == 0) ? 0 : wsum[w - 1]) + (inc - s);
    #pragma unroll
    for (int i = 0; i < 10; ++i) {
        const int idx = base + i;
        if (idx < N) g_offs[idx] = run, run += loc[i];
    }
    if (t == 0) g_offs[N] = E;
}

// ---------------- K3: scatter edges into CSR order (NO atomics) ----------------
__global__ __launch_bounds__(256) void k_scatter(
    const int* __restrict__ src, const int* __restrict__ dst, int E)
{
    const int base = (blockIdx.x * blockDim.x + threadIdx.x) * 4;
    if (base + 3 < E) {
        const int4 d = *reinterpret_cast<const int4*>(dst + base);
        const int4 s = *reinterpret_cast<const int4*>(src + base);
        const int4 r = *reinterpret_cast<const int4*>(g_rank + base);
        g_srcsorted[g_offs[d.x] + r.x] = s.x;
        g_srcsorted[g_offs[d.y] + r.y] = s.y;
        g_srcsorted[g_offs[d.z] + r.z] = s.z;
        g_srcsorted[g_offs[d.w] + r.w] = s.w;
    } else {
        for (int e = base; e < E; ++e)
            g_srcsorted[g_offs[dst[e]] + g_rank[e]] = src[e];
    }
}

// ---------------- K4: fused attention + residual + LayerNorm -------------------
// One warp per node, HALF-WARP PER EDGE: lanes [0,16) do edge j, [16,32) edge
// j+1. Lane g=lane&15 owns dims [8g, 8g+8) (one uint4 of fp16 K and of V).
// Head of that chunk = g>>2; score reduce = 2 shfl within the 4-lane group.
// Halves merged once at the end via xor-16 shuffles.
__global__ __launch_bounds__(256) void k_attn(
    const float* __restrict__ gamma, const float* __restrict__ beta,
    float* __restrict__ out, int N)
{
    const unsigned FULL = 0xffffffffu;
    const int warp = (blockIdx.x * blockDim.x + threadIdx.x) >> 5;
    if (warp >= N) return;
    const int lane = threadIdx.x & 31;
    const int g = lane & 15;
    const int half_id = lane >> 4;

    // q: 8 fp16 dims (pre-scaled) for this lane's chunk
    const uint4 qv = ((const uint4*)g_Qh)[warp * 16 + g];
    const __half2* qh = (const __half2*)&qv;

    const uint4* __restrict__ KV4 = (const uint4*)g_KV;  // 32 uint4/node: K then V

    float acc[8] = {0.f, 0.f, 0.f, 0.f, 0.f, 0.f, 0.f, 0.f};
    float ssum = 0.f;

    const int beg = g_offs[warp];
    const int end = g_offs[warp + 1];

    for (int base = beg; base < end; base += 32) {
        const int idx = base + lane;
        const int mysrc = (idx < end) ? g_srcsorted[idx] : 0;
        const int cnt = min(32, end - base);
        #pragma unroll 2
        for (int j = 0; j < cnt; j += 2) {
            const int el = j + half_id;                 // this half-warp's edge
            const int src = __shfl_sync(FULL, mysrc, el & 31);
            const uint4 ku = KV4[src * 32 + g];
            const uint4 vu = KV4[src * 32 + 16 + g];
            const __half2* kh = (const __half2*)&ku;
            __half2 d0 = __hmul2(qh[0], kh[0]);
            __half2 d1 = __hmul2(qh[1], kh[1]);
            d0 = __hfma2(qh[2], kh[2], d0);
            d1 = __hfma2(qh[3], kh[3], d1);
            const float2 pf = __half22float2(__hadd2(d0, d1));
            float p = pf.x + pf.y;
            p += __shfl_xor_sync(FULL, p, 1);
            p += __shfl_xor_sync(FULL, p, 2);
            const float w = (el < cnt) ? __expf(p) : 0.f;
            ssum += w;
            const __half2* vh = (const __half2*)&vu;
            #pragma unroll
            for (int i = 0; i < 4; ++i) {
                const float2 vf = __half22float2(vh[i]);
                acc[2 * i]     = fmaf(w, vf.x, acc[2 * i]);
                acc[2 * i + 1] = fmaf(w, vf.y, acc[2 * i + 1]);
            }
        }
    }

    // merge the two half-warps
    ssum += __shfl_xor_sync(FULL, ssum, 16);
    #pragma unroll
    for (int i = 0; i < 8; ++i) acc[i] += __shfl_xor_sync(FULL, acc[i], 16);

    const float inv = 1.f / (ssum + 1e-12f);
    // lane writes dims [8g + 4*half_id, +4)
    const int vecIdx = warp * 32 + g * 2 + half_id;
    const float4 r = ((const float4*)g_R)[vecIdx];
    const float* ah = acc + 4 * half_id;
    float4 h;
    h.x = fmaf(ah[0], inv, r.x);
    h.y = fmaf(ah[1], inv, r.y);
    h.z = fmaf(ah[2], inv, r.z);
    h.w = fmaf(ah[3], inv, r.w);

    float s1 = h.x + h.y + h.z + h.w;
    float s2 = h.x * h.x + h.y * h.y + h.z * h.z + h.w * h.w;
    #pragma unroll
    for (int o = 16; o; o >>= 1) {
        s1 += __shfl_xor_sync(FULL, s1, o);
        s2 += __shfl_xor_sync(FULL, s2, o);
    }
    const float mu  = s1 * (1.f / 128.f);
    const float var = s2 * (1.f / 128.f) - mu * mu;
    const float rs  = rsqrtf(var + LN_EPS);

    const float4 gg = ((const float4*)gamma)[g * 2 + half_id];
    const float4 bb = ((const float4*)beta)[g * 2 + half_id];
    float4 o4;
    o4.x = fmaf(gg.x * (h.x - mu), rs, bb.x);
    o4.y = fmaf(gg.y * (h.y - mu), rs, bb.y);
    o4.z = fmaf(gg.z * (h.z - mu), rs, bb.z);
    o4.w = fmaf(gg.w * (h.w - mu), rs, bb.w);
    ((float4*)out)[vecIdx] = o4;
}

// ---------------- launch -------------------------------------------------------
extern "C" void kernel_launch(void* const* d_in, const int* in_sizes, int n_in,
                              void* d_out, int out_size)
{
    const float* nodes = (const float*)d_in[0];
    const float* WQ    = (const float*)d_in[1];
    const float* WK    = (const float*)d_in[2];
    const float* WV    = (const float*)d_in[3];
    const float* WR    = (const float*)d_in[4];
    const float* br    = (const float*)d_in[5];
    const float* gamma = (const float*)d_in[6];
    const float* beta  = (const float*)d_in[7];
    const int*   ei    = (const int*)d_in[8];

    const int N = in_sizes[0] / F_DIM;
    const int E = in_sizes[8] / 2;
    const int* src = ei;
    const int* dst = ei + E;

    const int mblocks = (N + MBLK - 1) / MBLK;
    const int padN    = mblocks * MBLK;
    const int nblk    = mblocks * 8;
    const int epb     = (E + nblk - 1) / nblk;

    void* cnt_ptr = nullptr;
    cudaGetSymbolAddress(&cnt_ptr, g_counts);
    cudaMemsetAsync(cnt_ptr, 0, N * sizeof(int));

    k_copyX<<<(padN * F_DIM + 255) / 256, 256>>>(nodes, N, padN);
    dim3 grid_tc(mblocks, 8);
    k_qkv_tc<<<grid_tc, 128>>>(WQ, WK, WV, WR, br, dst, N, E, epb);
    k_scan<<<1, 1024>>>(N, E);
    k_scatter<<<((E + 3) / 4 + 255) / 256, 256>>>(src, dst, E);
    k_attn<<<(N + 7) / 8, 256>>>(gamma, beta, (float*)d_out, N);
}